// round 6
// baseline (speedup 1.0000x reference)
#include <cuda_runtime.h>
#include <cuda_bf16.h>

#define NN 20000
#define NE 100000
#define NG 64

// ---------------- device scratch (static; no runtime allocation) -------------
__device__ float g_S1[NN * 260];
__device__ float g_h1[NN * 64];
__device__ float g_t[NN * 64];
__device__ float g_R[NN * 64];
__device__ float g_Q[163840000];     // [NN][8192]
__device__ float g_Bperm[64 * 8192];
__device__ float g_agg2[NN * 64];
__device__ int   g_deg[NN];
__device__ int   g_outdeg[NN];
__device__ int   g_rowstart[NN + 1];
__device__ int   g_cursor[NN];
__device__ int   g_ebysrc[NE];
__device__ float g_pool[NG * 64];
__device__ int   g_gcnt[NG];

// ---------------- kernels ----------------------------------------------------
__global__ void k_zero() {
    int i = blockIdx.x * blockDim.x + threadIdx.x;
    int st = gridDim.x * blockDim.x;
    for (int j = i; j < NN * 260; j += st) g_S1[j] = 0.f;
    for (int j = i; j < NN * 64; j += st) g_agg2[j] = 0.f;
    for (int j = i; j < NG * 64; j += st) g_pool[j] = 0.f;
    for (int j = i; j < NN; j += st) { g_deg[j] = 0; g_outdeg[j] = 0; g_cursor[j] = 0; }
    for (int j = i; j < NG; j += st) g_gcnt[j] = 0;
}

// layer1 edges: z1 = relu(ea@eW1_1+eb1_1); scatter z1 (x) x_src, and x_src; count degs
__global__ void k_l1_edge(const int* __restrict__ ei, const float* __restrict__ ea,
                          const float* __restrict__ x,
                          const float* __restrict__ eW1, const float* __restrict__ eb1) {
    int t = threadIdx.x;                 // 256 = 4 edges x 64
    int k = t & 63;
    int e = blockIdx.x * 4 + (t >> 6);   // 25000*4 = 100000
    int src = ei[e], dst = ei[NE + e];
    float a0 = ea[e * 4 + 0], a1 = ea[e * 4 + 1], a2 = ea[e * 4 + 2], a3 = ea[e * 4 + 3];
    float z = eb1[k] + a0 * eW1[k] + a1 * eW1[64 + k] + a2 * eW1[128 + k] + a3 * eW1[192 + k];
    z = fmaxf(z, 0.f);
    float x0 = x[src * 4 + 0], x1 = x[src * 4 + 1], x2 = x[src * 4 + 2], x3 = x[src * 4 + 3];
    float* S = g_S1 + dst * 260;
    atomicAdd(S + k * 4 + 0, z * x0);
    atomicAdd(S + k * 4 + 1, z * x1);
    atomicAdd(S + k * 4 + 2, z * x2);
    atomicAdd(S + k * 4 + 3, z * x3);
    if (k < 4) atomicAdd(S + 256 + k, x[src * 4 + k]);
    if (k == 0) { atomicAdd(&g_deg[dst], 1); atomicAdd(&g_outdeg[src], 1); }
}

// exclusive scan of outdeg -> rowstart; single block of 1024
__global__ void k_scan() {
    __shared__ int wsum[32];
    __shared__ int carry;
    int t = threadIdx.x, lane = t & 31, wid = t >> 5;
    if (t == 0) carry = 0;
    __syncthreads();
    for (int base = 0; base < NN; base += 1024) {
        int i = base + t;
        int v = (i < NN) ? g_outdeg[i] : 0;
        int incl = v;
        #pragma unroll
        for (int d = 1; d < 32; d <<= 1) {
            int y = __shfl_up_sync(0xffffffffu, incl, d);
            if (lane >= d) incl += y;
        }
        if (lane == 31) wsum[wid] = incl;
        __syncthreads();
        if (wid == 0) {
            int wv = wsum[lane];
            #pragma unroll
            for (int d = 1; d < 32; d <<= 1) {
                int y = __shfl_up_sync(0xffffffffu, wv, d);
                if (lane >= d) wv += y;
            }
            wsum[lane] = wv;
        }
        __syncthreads();
        int pre = ((wid > 0) ? wsum[wid - 1] : 0) + carry;
        if (i < NN) g_rowstart[i] = pre + incl - v;
        __syncthreads();
        if (t == 0) carry += wsum[31];
        __syncthreads();
    }
    if (t == 0) g_rowstart[NN] = carry;
}

__global__ void k_fill(const int* __restrict__ ei) {
    int e = blockIdx.x * blockDim.x + threadIdx.x;
    if (e < NE) {
        int src = ei[e];
        int p = atomicAdd(&g_cursor[src], 1);
        g_ebysrc[g_rowstart[src] + p] = e;
    }
}

// layer1 node: contract S1 with eW2_1 (+ Sx with eb2_1), /deg, + x@root1 + bias1, relu
__global__ void k_l1_node(const float* __restrict__ eW2, const float* __restrict__ eb2,
                          const float* __restrict__ x, const float* __restrict__ root1,
                          const float* __restrict__ bias1) {
    __shared__ float sS[16 * 260];
    int o = threadIdx.x;                 // 64
    int v0 = blockIdx.x * 16;            // 1250*16 = 20000
    for (int l = o; l < 16 * 260; l += 64) sS[l] = g_S1[v0 * 260 + l];
    __syncthreads();
    float acc[16];
    #pragma unroll
    for (int n = 0; n < 16; n++) acc[n] = 0.f;
    for (int k = 0; k < 64; k++) {
        #pragma unroll
        for (int i = 0; i < 4; i++) {
            float w = eW2[k * 256 + i * 64 + o];
            #pragma unroll
            for (int n = 0; n < 16; n++) acc[n] += sS[n * 260 + k * 4 + i] * w;
        }
    }
    #pragma unroll
    for (int i = 0; i < 4; i++) {
        float w = eb2[i * 64 + o];
        #pragma unroll
        for (int n = 0; n < 16; n++) acc[n] += sS[n * 260 + 256 + i] * w;
    }
    for (int n = 0; n < 16; n++) {
        int v = v0 + n;
        float d = fmaxf((float)g_deg[v], 1.f);
        float r = bias1[o];
        #pragma unroll
        for (int i = 0; i < 4; i++) r += x[v * 4 + i] * root1[i * 64 + o];
        g_t[v * 64 + o] = fmaxf(acc[n] / d + r, 0.f);
    }
}

// layernorm g_t -> g_h1 (one warp per node)
__global__ void k_ln1(const float* __restrict__ gam, const float* __restrict__ bet) {
    int lane = threadIdx.x & 31;
    int v = blockIdx.x * 8 + (threadIdx.x >> 5);
    if (v >= NN) return;
    float t0 = g_t[v * 64 + lane], t1 = g_t[v * 64 + 32 + lane];
    float s = t0 + t1;
    #pragma unroll
    for (int d = 16; d; d >>= 1) s += __shfl_xor_sync(0xffffffffu, s, d);
    float mu = s * (1.f / 64.f);
    float d0 = t0 - mu, d1 = t1 - mu;
    float q = d0 * d0 + d1 * d1;
    #pragma unroll
    for (int d = 16; d; d >>= 1) q += __shfl_xor_sync(0xffffffffu, q, d);
    float rs = rsqrtf(q * (1.f / 64.f) + 1e-5f);
    g_h1[v * 64 + lane]      = d0 * rs * gam[lane] + bet[lane];
    g_h1[v * 64 + 32 + lane] = d1 * rs * gam[32 + lane] + bet[32 + lane];
}

// Bperm[i][k*64+o] = eW2_2[k][i*64+o]
__global__ void k_bperm(const float* __restrict__ W) {
    int idx = blockIdx.x * blockDim.x + threadIdx.x;
    if (idx < 64 * 8192) {
        int o = idx & 63, k = (idx >> 6) & 127, i = idx >> 13;
        g_Bperm[i * 8192 + k * 64 + o] = W[k * 4096 + i * 64 + o];
    }
}

// R[v][o] = sum_i h1[v][i] * eb2_2[i*64+o]
__global__ void k_rgemm(const float* __restrict__ eb2) {
    __shared__ float sw[4096];
    int o = threadIdx.x;                 // 64
    for (int j = o; j < 4096; j += 64) sw[j] = eb2[j];
    __syncthreads();
    int v0 = blockIdx.x * 8;             // 2500*8
    for (int n = 0; n < 8; n++) {
        int v = v0 + n;
        float acc = 0.f;
        #pragma unroll 8
        for (int i = 0; i < 64; i++) acc += g_h1[v * 64 + i] * sw[i * 64 + o];
        g_R[v * 64 + o] = acc;
    }
}

// Q = h1 [20000x64] @ Bperm [64x8192]; tiles 32x128, 256 threads, thread tile 4x4
__global__ void __launch_bounds__(256) k_qgemm() {
    __shared__ float sA[64 * 36];        // sA[k*36+m] = h1[v0+m][k]
    __shared__ float sB[64 * 128];
    int t = threadIdx.x;
    int v0 = blockIdx.x * 32;            // 625*32 = 20000
    int c0 = blockIdx.y * 128;           // 64*128 = 8192
    for (int idx = t; idx < 2048; idx += 256) {
        int k = idx & 63, m = idx >> 6;
        sA[k * 36 + m] = g_h1[(v0 + m) * 64 + k];
    }
    for (int idx = t; idx < 8192; idx += 256) {
        int k = idx >> 7, c = idx & 127;
        sB[k * 128 + c] = g_Bperm[k * 8192 + c0 + c];
    }
    __syncthreads();
    int tx = t & 31, ty = t >> 5;
    int n = tx * 4, m = ty * 4;
    float4 acc0 = {0,0,0,0}, acc1 = {0,0,0,0}, acc2 = {0,0,0,0}, acc3 = {0,0,0,0};
    #pragma unroll 16
    for (int k = 0; k < 64; k++) {
        float4 b = *(const float4*)(sB + k * 128 + n);
        float4 a = *(const float4*)(sA + k * 36 + m);
        acc0.x += a.x * b.x; acc0.y += a.x * b.y; acc0.z += a.x * b.z; acc0.w += a.x * b.w;
        acc1.x += a.y * b.x; acc1.y += a.y * b.y; acc1.z += a.y * b.z; acc1.w += a.y * b.w;
        acc2.x += a.z * b.x; acc2.y += a.z * b.y; acc2.z += a.z * b.z; acc2.w += a.z * b.w;
        acc3.x += a.w * b.x; acc3.y += a.w * b.y; acc3.z += a.w * b.z; acc3.w += a.w * b.w;
    }
    size_t base = (size_t)(v0 + m) * 8192 + c0 + n;
    *(float4*)(g_Q + base)            = acc0;
    *(float4*)(g_Q + base + 8192)     = acc1;
    *(float4*)(g_Q + base + 2 * 8192) = acc2;
    *(float4*)(g_Q + base + 3 * 8192) = acc3;
}

// layer2 edge pass: one CTA per src node; Q row in smem; per-edge z2 then msg scatter
__global__ void __launch_bounds__(128) k_l2_edge(const int* __restrict__ ei,
                                                 const float* __restrict__ ea,
                                                 const float* __restrict__ eW1,
                                                 const float* __restrict__ eb1) {
    __shared__ float sQ[8192];
    __shared__ float sR[64];
    __shared__ float sz[128];
    __shared__ float4 sred4[128];
    int v = blockIdx.x;
    int r0 = g_rowstart[v], r1 = g_rowstart[v + 1];
    if (r0 == r1) return;
    int t = threadIdx.x;                 // 128
    const float* Qrow = g_Q + (size_t)v * 8192;
    for (int j = t; j < 2048; j += 128) ((float4*)sQ)[j] = ((const float4*)Qrow)[j];
    if (t < 64) sR[t] = g_R[v * 64 + t];
    float w0 = eW1[t], w1 = eW1[128 + t], w2 = eW1[256 + t], w3 = eW1[384 + t];
    float bz = eb1[t];
    int o4 = (t & 15) * 4, h = t >> 4;
    __syncthreads();
    for (int p = r0; p < r1; p++) {
        int e = g_ebysrc[p];
        int dst = ei[NE + e];
        float a0 = ea[e * 4], a1 = ea[e * 4 + 1], a2 = ea[e * 4 + 2], a3 = ea[e * 4 + 3];
        sz[t] = fmaxf(bz + a0 * w0 + a1 * w1 + a2 * w2 + a3 * w3, 0.f);
        __syncthreads();
        float4 acc = {0,0,0,0};
        int kb = h * 16;
        #pragma unroll
        for (int kk = 0; kk < 16; kk++) {
            float s = sz[kb + kk];
            float4 q = *(const float4*)(sQ + (kb + kk) * 64 + o4);
            acc.x += s * q.x; acc.y += s * q.y; acc.z += s * q.z; acc.w += s * q.w;
        }
        sred4[t] = acc;
        __syncthreads();
        if (t < 16) {
            float4 m = sred4[t];
            #pragma unroll
            for (int hh = 1; hh < 8; hh++) {
                float4 u = sred4[hh * 16 + t];
                m.x += u.x; m.y += u.y; m.z += u.z; m.w += u.w;
            }
            int o = t * 4;
            atomicAdd(&g_agg2[dst * 64 + o],     m.x + sR[o]);
            atomicAdd(&g_agg2[dst * 64 + o + 1], m.y + sR[o + 1]);
            atomicAdd(&g_agg2[dst * 64 + o + 2], m.z + sR[o + 2]);
            atomicAdd(&g_agg2[dst * 64 + o + 3], m.w + sR[o + 3]);
        }
        __syncthreads();
    }
}

// layer2 node: agg2/deg + h1@root2 + bias2, relu
__global__ void k_l2_node(const float* __restrict__ root2, const float* __restrict__ bias2) {
    __shared__ float sw[4096];
    int o = threadIdx.x;                 // 64
    for (int j = o; j < 4096; j += 64) sw[j] = root2[j];
    __syncthreads();
    int v0 = blockIdx.x * 8;             // 2500*8
    for (int n = 0; n < 8; n++) {
        int v = v0 + n;
        float acc = bias2[o];
        #pragma unroll 8
        for (int i = 0; i < 64; i++) acc += g_h1[v * 64 + i] * sw[i * 64 + o];
        float d = fmaxf((float)g_deg[v], 1.f);
        g_t[v * 64 + o] = fmaxf(g_agg2[v * 64 + o] / d + acc, 0.f);
    }
}

// layernorm2 + global mean pool scatter
__global__ void k_ln2pool(const float* __restrict__ gam, const float* __restrict__ bet,
                          const int* __restrict__ batch) {
    int lane = threadIdx.x & 31;
    int v = blockIdx.x * 8 + (threadIdx.x >> 5);
    if (v >= NN) return;
    float t0 = g_t[v * 64 + lane], t1 = g_t[v * 64 + 32 + lane];
    float s = t0 + t1;
    #pragma unroll
    for (int d = 16; d; d >>= 1) s += __shfl_xor_sync(0xffffffffu, s, d);
    float mu = s * (1.f / 64.f);
    float d0 = t0 - mu, d1 = t1 - mu;
    float q = d0 * d0 + d1 * d1;
    #pragma unroll
    for (int d = 16; d; d >>= 1) q += __shfl_xor_sync(0xffffffffu, q, d);
    float rs = rsqrtf(q * (1.f / 64.f) + 1e-5f);
    float y0 = d0 * rs * gam[lane] + bet[lane];
    float y1 = d1 * rs * gam[32 + lane] + bet[32 + lane];
    int b = batch[v];
    atomicAdd(&g_pool[b * 64 + lane], y0);
    atomicAdd(&g_pool[b * 64 + 32 + lane], y1);
    if (lane == 0) atomicAdd(&g_gcnt[b], 1);
}

__global__ void k_out(float* __restrict__ out) {
    int i = blockIdx.x * blockDim.x + threadIdx.x;
    if (i < NG * 64) {
        float c = fmaxf((float)g_gcnt[i >> 6], 1.f);
        out[i] = g_pool[i] / c;
    }
}

// ---------------- launch ------------------------------------------------------
extern "C" void kernel_launch(void* const* d_in, const int* in_sizes, int n_in,
                              void* d_out, int out_size) {
    const float* x      = (const float*)d_in[0];
    const int*   ei     = (const int*)  d_in[1];
    const float* ea     = (const float*)d_in[2];
    const int*   batch  = (const int*)  d_in[3];
    const float* eW1_1  = (const float*)d_in[4];
    const float* eb1_1  = (const float*)d_in[5];
    const float* eW2_1  = (const float*)d_in[6];
    const float* eb2_1  = (const float*)d_in[7];
    const float* root1  = (const float*)d_in[8];
    const float* bias1  = (const float*)d_in[9];
    const float* g1     = (const float*)d_in[10];
    const float* b1     = (const float*)d_in[11];
    const float* eW1_2  = (const float*)d_in[12];
    const float* eb1_2  = (const float*)d_in[13];
    const float* eW2_2  = (const float*)d_in[14];
    const float* eb2_2  = (const float*)d_in[15];
    const float* root2  = (const float*)d_in[16];
    const float* bias2  = (const float*)d_in[17];
    const float* g2     = (const float*)d_in[18];
    const float* b2     = (const float*)d_in[19];
    float* out = (float*)d_out;

    k_zero<<<2048, 256>>>();
    k_l1_edge<<<NE / 4, 256>>>(ei, ea, x, eW1_1, eb1_1);
    k_scan<<<1, 1024>>>();
    k_fill<<<(NE + 255) / 256, 256>>>(ei);
    k_l1_node<<<NN / 16, 64>>>(eW2_1, eb2_1, x, root1, bias1);
    k_ln1<<<NN / 8, 256>>>(g1, b1);
    k_bperm<<<(64 * 8192 + 255) / 256, 256>>>(eW2_2);
    k_rgemm<<<NN / 8, 64>>>(eb2_2);
    k_qgemm<<<dim3(NN / 32, 64), 256>>>();
    k_l2_edge<<<NN, 128>>>(ei, ea, eW1_2, eb1_2);
    k_l2_node<<<NN / 8, 64>>>(root2, bias2);
    k_ln2pool<<<NN / 8, 256>>>(g2, b2, batch);
    k_out<<<(NG * 64 + 255) / 256, 256>>>(out);
}